// round 5
// baseline (speedup 1.0000x reference)
#include <cuda_runtime.h>

// FourierBlock: out[b,n,h,e,l] = irfft3bins( einsum(rfft(q)[bins 1,4,5], W1+iW2) )
// q: (B=8, N=2000, L=64, H=4, E=16)  -> slab layout [l][h*16+e]
// out: (B, N, H, E, L)               -> slab layout [h*16+e][l]  (L innermost)
// weights: (N, H, E, E, M=3). k, v, mask unused by the forward pass.

#define NB 8
#define NN 2000
#define SLAB 4096      // floats per (b,n) slab
#define WNODE 3072     // H*E*E*M floats per node per weight tensor

// cos(2*pi*k/64); sin(2*pi*k/64) = COS64[(k+48)&63]
__device__ const float COS64[64] = {
     1.000000000f,  0.995184727f,  0.980785280f,  0.956940336f,
     0.923879533f,  0.881921264f,  0.831469612f,  0.773010453f,
     0.707106781f,  0.634393284f,  0.555570233f,  0.471396737f,
     0.382683432f,  0.290284677f,  0.195090322f,  0.098017140f,
     0.000000000f, -0.098017140f, -0.195090322f, -0.290284677f,
    -0.382683432f, -0.471396737f, -0.555570233f, -0.634393284f,
    -0.707106781f, -0.773010453f, -0.831469612f, -0.881921264f,
    -0.923879533f, -0.956940336f, -0.980785280f, -0.995184727f,
    -1.000000000f, -0.995184727f, -0.980785280f, -0.956940336f,
    -0.923879533f, -0.881921264f, -0.831469612f, -0.773010453f,
    -0.707106781f, -0.634393284f, -0.555570233f, -0.471396737f,
    -0.382683432f, -0.290284677f, -0.195090322f, -0.098017140f,
     0.000000000f,  0.098017140f,  0.195090322f,  0.290284677f,
     0.382683432f,  0.471396737f,  0.555570233f,  0.634393284f,
     0.707106781f,  0.773010453f,  0.831469612f,  0.881921264f,
     0.923879533f,  0.956940336f,  0.980785280f,  0.995184727f
};

// Transposed weights: T[n][m][i4][ho][ii] ; element = W[n, h=ho>>4, i=4*i4+ii, o=ho&15, m]
__device__ float g_wT1[NN * WNODE];
__device__ float g_wT2[NN * WNODE];

// ---------------------------------------------------------------------------
// Pre-kernel: transpose weights into coalesced-consumable layout (once/launch)
// ---------------------------------------------------------------------------
__global__ __launch_bounds__(256) void transpose_w_kernel(
    const float* __restrict__ w1, const float* __restrict__ w2)
{
    const int n   = blockIdx.x;
    const int tid = threadIdx.x;
    __shared__ float s1[WNODE];
    __shared__ float s2[WNODE];

    const float4* a4 = (const float4*)(w1 + (size_t)n * WNODE);
    const float4* b4 = (const float4*)(w2 + (size_t)n * WNODE);
    #pragma unroll
    for (int r = 0; r < 3; ++r) {
        ((float4*)s1)[tid + 256 * r] = a4[tid + 256 * r];
        ((float4*)s2)[tid + 256 * r] = b4[tid + 256 * r];
    }
    __syncthreads();

    float4* o1 = (float4*)g_wT1 + (size_t)n * 768;
    float4* o2 = (float4*)g_wT2 + (size_t)n * 768;
    #pragma unroll
    for (int r = 0; r < 3; ++r) {
        int g  = tid + 256 * r;          // output float4 index within node
        int m  = g >> 8;                  // 0..2
        int i4 = (g >> 6) & 3;            // 0..3
        int ho = g & 63;                  // h*16+o
        int h  = ho >> 4, o = ho & 15;
        float4 u, w;
        float* up = &u.x; float* wp = &w.x;
        #pragma unroll
        for (int ii = 0; ii < 4; ++ii) {
            int i   = i4 * 4 + ii;
            int src = (h * 256 + i * 16 + o) * 3 + m;
            up[ii] = s1[src];
            wp[ii] = s2[src];
        }
        o1[g] = u;
        o2[g] = w;
    }
}

// ---------------------------------------------------------------------------
// Main kernel: one CTA per (b, n); b fastest so 8 CTAs share a node's weights
// ---------------------------------------------------------------------------
__global__ __launch_bounds__(256) void fourier_main_kernel(
    const float* __restrict__ q,
    float* __restrict__ out)
{
    const int b    = blockIdx.x;
    const int n    = blockIdx.y;
    const int tid  = threadIdx.x;
    const int lane = tid & 31;
    const int warp = tid >> 5;
    const int c    = tid & 15;   // float4 column (ho group of 4)
    const int p    = tid >> 4;   // row group: l = 4p..4p+3

    __shared__ float  sTw[64];
    __shared__ float4 sXp4[8][6][16];   // per-warp partial X
    __shared__ float  sX[6][64];        // X[2m+{re,im}][h*16+i]
    __shared__ float  sY[6][64];        // Y[2m+{re,im}][h*16+o]

    if (tid < 64) sTw[tid] = COS64[tid];

    const size_t slab = ((size_t)b * NN + n) * SLAB;

    // batch the 4 LDG.128 up front
    float4 v[4];
    {
        const float4* q4 = (const float4*)(q + slab);
        #pragma unroll
        for (int j = 0; j < 4; ++j)
            v[j] = q4[(4 * p + j) * 16 + c];
    }
    __syncthreads();   // sTw visible

    // ---- 3-bin DFT over this thread's 4 rows; twiddles by register recurrence ----
    // step rotations e^{-i*2pi*f/64} for f = {1,4,5} (literals)
    const float CF0 = 0.995184727f, SF0 = 0.098017140f;  // f=1
    const float CF1 = 0.923879533f, SF1 = 0.382683432f;  // f=4
    const float CF2 = 0.881921264f, SF2 = 0.471396737f;  // f=5
    float cB0, sB0, cB1, sB1, cB2, sB2;
    {
        int l0 = 4 * p;
        int k0 = (1 * l0) & 63, k1 = (4 * l0) & 63, k2 = (5 * l0) & 63;
        cB0 = sTw[k0]; sB0 = -sTw[(k0 + 48) & 63];
        cB1 = sTw[k1]; sB1 = -sTw[(k1 + 48) & 63];
        cB2 = sTw[k2]; sB2 = -sTw[(k2 + 48) & 63];
    }

    float ar[3][4], ai[3][4];
    #pragma unroll
    for (int m = 0; m < 3; ++m)
        #pragma unroll
        for (int x = 0; x < 4; ++x) { ar[m][x] = 0.f; ai[m][x] = 0.f; }

    #pragma unroll
    for (int j = 0; j < 4; ++j) {
        const float* vv = &v[j].x;
        #pragma unroll
        for (int x = 0; x < 4; ++x) {
            float xv = vv[x];
            ar[0][x] = fmaf(xv, cB0, ar[0][x]);  ai[0][x] = fmaf(xv, sB0, ai[0][x]);
            ar[1][x] = fmaf(xv, cB1, ar[1][x]);  ai[1][x] = fmaf(xv, sB1, ai[1][x]);
            ar[2][x] = fmaf(xv, cB2, ar[2][x]);  ai[2][x] = fmaf(xv, sB2, ai[2][x]);
        }
        if (j < 3) {
            float t;
            t = fmaf(cB0, CF0,  sB0 * SF0);  sB0 = fmaf(sB0, CF0, -cB0 * SF0);  cB0 = t;
            t = fmaf(cB1, CF1,  sB1 * SF1);  sB1 = fmaf(sB1, CF1, -cB1 * SF1);  cB1 = t;
            t = fmaf(cB2, CF2,  sB2 * SF2);  sB2 = fmaf(sB2, CF2, -cB2 * SF2);  cB2 = t;
        }
    }

    // combine the two p-groups in one warp, write per-warp partials
    #pragma unroll
    for (int m = 0; m < 3; ++m)
        #pragma unroll
        for (int x = 0; x < 4; ++x) {
            ar[m][x] += __shfl_xor_sync(0xffffffffu, ar[m][x], 16);
            ai[m][x] += __shfl_xor_sync(0xffffffffu, ai[m][x], 16);
        }
    if (lane < 16) {
        #pragma unroll
        for (int m = 0; m < 3; ++m) {
            sXp4[warp][2 * m    ][lane] = make_float4(ar[m][0], ar[m][1], ar[m][2], ar[m][3]);
            sXp4[warp][2 * m + 1][lane] = make_float4(ai[m][0], ai[m][1], ai[m][2], ai[m][3]);
        }
    }
    __syncthreads();

    const int m_ = tid >> 6;     // 0..2 (valid for tid<192)
    const int ho = tid & 63;
    const int h  = ho >> 4;

    // ---- reduce 8 warp-partials -> X ----
    if (tid < 192) {
        const float* sf = (const float*)sXp4;
        float xr = 0.f, xi = 0.f;
        #pragma unroll
        for (int w = 0; w < 8; ++w) {
            xr += sf[w * 384 + (2 * m_    ) * 64 + ho];
            xi += sf[w * 384 + (2 * m_ + 1) * 64 + ho];
        }
        sX[2 * m_    ][ho] = xr;
        sX[2 * m_ + 1][ho] = xi;
    }
    __syncthreads();

    // ---- C: complex 16x16 channel mix; weights via coalesced float4 loads ----
    if (tid < 192) {
        const float4* wR = (const float4*)g_wT1 + ((size_t)(n * 3 + m_) * 4) * 64 + ho;
        const float4* wI = (const float4*)g_wT2 + ((size_t)(n * 3 + m_) * 4) * 64 + ho;
        float yr = 0.f, yi = 0.f;
        #pragma unroll
        for (int i4 = 0; i4 < 4; ++i4) {
            float4 a = __ldg(wR + i4 * 64);
            float4 d = __ldg(wI + i4 * 64);
            const float* ap = &a.x; const float* dp = &d.x;
            #pragma unroll
            for (int ii = 0; ii < 4; ++ii) {
                float xr = sX[2 * m_    ][(h << 4) + i4 * 4 + ii];
                float xi = sX[2 * m_ + 1][(h << 4) + i4 * 4 + ii];
                yr = fmaf(xr, ap[ii], yr);  yr = fmaf(-xi, dp[ii], yr);
                yi = fmaf(xr, dp[ii], yi);  yi = fmaf( xi, ap[ii], yi);
            }
        }
        sY[2 * m_    ][ho] = yr;
        sY[2 * m_ + 1][ho] = yi;
    }
    __syncthreads();

    // ---- D: 3-bin inverse transform; twiddle recurrence; coalesced stores ----
    // out[ho][l] = y0/64 + (2/64)*(y1r*cos(t l) - y1i*sin(t l) + y2r*cos(2 t l) - y2i*sin(2 t l))
    float c1, s1, c2, s2;
    {
        int l0 = (tid & 15) << 2;
        c1 = sTw[l0];             s1 = sTw[(l0 + 48) & 63];
        c2 = sTw[(2 * l0) & 63];  s2 = sTw[(2 * l0 + 48) & 63];
    }
    const float R1C = 0.995184727f, R1S = 0.098017140f;   // e^{+i*2pi/64}
    const float R2C = 0.980785280f, R2S = 0.195090322f;   // e^{+i*4pi/64}

    float4* o4 = (float4*)(out + slab);
    #pragma unroll
    for (int r = 0; r < 4; ++r) {
        int f4i = tid + (r << 8);
        int hd  = f4i >> 4;
        float y0  = sY[0][hd] * 0.015625f;
        float y1r = sY[2][hd] * 0.03125f, y1i = sY[3][hd] * 0.03125f;
        float y2r = sY[4][hd] * 0.03125f, y2i = sY[5][hd] * 0.03125f;
        float cc1 = c1, ss1 = s1, cc2 = c2, ss2 = s2;
        float4 vv4;  float* vv = &vv4.x;
        #pragma unroll
        for (int j = 0; j < 4; ++j) {
            float acc = y0;
            acc = fmaf(y1r, cc1, acc);  acc = fmaf(-y1i, ss1, acc);
            acc = fmaf(y2r, cc2, acc);  acc = fmaf(-y2i, ss2, acc);
            vv[j] = acc;
            if (j < 3) {
                float t;
                t = fmaf(cc1, R1C, -ss1 * R1S);  ss1 = fmaf(ss1, R1C, cc1 * R1S);  cc1 = t;
                t = fmaf(cc2, R2C, -ss2 * R2S);  ss2 = fmaf(ss2, R2C, cc2 * R2S);  cc2 = t;
            }
        }
        o4[f4i] = vv4;
    }
}

extern "C" void kernel_launch(void* const* d_in, const int* in_sizes, int n_in,
                              void* d_out, int out_size)
{
    // metadata order: q, k, v, mask, weights1, weights2 (k, v, mask unused)
    const float* q  = (const float*)d_in[0];
    const float* w1 = (const float*)d_in[4];
    const float* w2 = (const float*)d_in[5];
    float* out = (float*)d_out;

    transpose_w_kernel<<<NN, 256>>>(w1, w2);
    dim3 grid(NB, NN);
    fourier_main_kernel<<<grid, 256>>>(q, out);
}

// round 6
// speedup vs baseline: 1.2659x; 1.2659x over previous
#include <cuda_runtime.h>

// FourierBlock: out = irfft3bins( einsum(rfft(q)[bins 1,4,5], W1+iW2) )
// q: (B=8, N=2000, L=64, H=4, E=16); weights (N,H,E,E,3). k,v,mask unused.
// One CTA per node, persistent over b, q-prefetch pipelined across iterations.

#define NB 8
#define NN 2000
#define SLAB 4096          // floats per (b,n) slab
#define WNODE 3072         // floats per node per weight tensor
#define WPAD 776           // padded per-h smem stride (768 + 8 banks)

// cos(2*pi*k/64); sin(2*pi*k/64) = COS64[(k+48)&63]
__device__ const float COS64[64] = {
     1.000000000f,  0.995184727f,  0.980785280f,  0.956940336f,
     0.923879533f,  0.881921264f,  0.831469612f,  0.773010453f,
     0.707106781f,  0.634393284f,  0.555570233f,  0.471396737f,
     0.382683432f,  0.290284677f,  0.195090322f,  0.098017140f,
     0.000000000f, -0.098017140f, -0.195090322f, -0.290284677f,
    -0.382683432f, -0.471396737f, -0.555570233f, -0.634393284f,
    -0.707106781f, -0.773010453f, -0.831469612f, -0.881921264f,
    -0.923879533f, -0.956940336f, -0.980785280f, -0.995184727f,
    -1.000000000f, -0.995184727f, -0.980785280f, -0.956940336f,
    -0.923879533f, -0.881921264f, -0.831469612f, -0.773010453f,
    -0.707106781f, -0.634393284f, -0.555570233f, -0.471396737f,
    -0.382683432f, -0.290284677f, -0.195090322f, -0.098017140f,
     0.000000000f,  0.098017140f,  0.195090322f,  0.290284677f,
     0.382683432f,  0.471396737f,  0.555570233f,  0.634393284f,
     0.707106781f,  0.773010453f,  0.831469612f,  0.881921264f,
     0.923879533f,  0.956940336f,  0.980785280f,  0.995184727f
};

__global__ __launch_bounds__(256) void fourier_pipe_kernel(
    const float* __restrict__ q,
    const float* __restrict__ w1,
    const float* __restrict__ w2,
    float* __restrict__ out)
{
    const int n    = blockIdx.x;
    const int tid  = threadIdx.x;
    const int lane = tid & 31;
    const int warp = tid >> 5;
    const int c    = tid & 15;    // float4 column (hi group of 4)
    const int p    = tid >> 4;    // l-row group: l = 4p..4p+3

    __shared__ float  sW1[4 * WPAD];     // raw weights, per-h padded
    __shared__ float  sW2[4 * WPAD];
    __shared__ float4 sXp4[8][6][16];    // per-warp DFT partials
    __shared__ float  sX[6][64];         // X[2m+{re,im}][h*16+i]
    __shared__ float  sY[6][64];         // Y[2m+{re,im}][h*16+o]

    const size_t bstr4 = (size_t)NN * (SLAB / 4);   // float4 stride per batch

    // ---- issue b=0 q loads first (critical path) ----
    float4 v[4];
    {
        const float4* q4 = (const float4*)q + (size_t)n * (SLAB / 4);
        #pragma unroll
        for (int j = 0; j < 4; ++j)
            v[j] = q4[(4 * p + j) * 16 + c];
    }

    // ---- cooperative weight stage: raw layout, coalesced, padded per h ----
    {
        const float4* a4 = (const float4*)(w1 + (size_t)n * WNODE);
        const float4* b4 = (const float4*)(w2 + (size_t)n * WNODE);
        #pragma unroll
        for (int r = 0; r < 3; ++r) {
            int g4  = tid + 256 * r;        // 0..767
            int h   = g4 / 192;
            int rem = g4 - h * 192;
            ((float4*)sW1)[h * (WPAD / 4) + rem] = a4[g4];
            ((float4*)sW2)[h * (WPAD / 4) + rem] = b4[g4];
        }
    }

    // ---- twiddle bases (once per CTA) ----
    const float CF0 = 0.995184727f, SF0 = 0.098017140f;   // e^{-i*2pi*1/64} step
    const float CF1 = 0.923879533f, SF1 = 0.382683432f;   // f=4
    const float CF2 = 0.881921264f, SF2 = 0.471396737f;   // f=5
    float cB0b, sB0b, cB1b, sB1b, cB2b, sB2b;
    {
        int l0 = 4 * p;
        int k0 = l0 & 63, k1 = (4 * l0) & 63, k2 = (5 * l0) & 63;
        cB0b = COS64[k0];  sB0b = -COS64[(k0 + 48) & 63];
        cB1b = COS64[k1];  sB1b = -COS64[(k1 + 48) & 63];
        cB2b = COS64[k2];  sB2b = -COS64[(k2 + 48) & 63];
    }
    const float R1C = 0.995184727f, R1S = 0.098017140f;   // e^{+i*2pi/64}
    const float R2C = 0.980785280f, R2S = 0.195090322f;   // e^{+i*4pi/64}
    float c1b, s1b, c2b, s2b;
    {
        int l0 = (tid & 15) << 2;
        c1b = COS64[l0];              s1b = COS64[(l0 + 48) & 63];
        c2b = COS64[(2 * l0) & 63];   s2b = COS64[(2 * l0 + 48) & 63];
    }

    const int m_ = tid >> 6;     // 0..2 (valid for tid < 192)
    const int ho = tid & 63;
    const int h  = ho >> 4;
    const int o  = ho & 15;

    for (int b = 0; b < NB; ++b) {
        // ---- 3-bin DFT of this batch's q (consume v) ----
        float cB0 = cB0b, sB0 = sB0b, cB1 = cB1b, sB1 = sB1b, cB2 = cB2b, sB2 = sB2b;
        float ar[3][4], ai[3][4];
        #pragma unroll
        for (int m = 0; m < 3; ++m)
            #pragma unroll
            for (int x = 0; x < 4; ++x) { ar[m][x] = 0.f; ai[m][x] = 0.f; }

        #pragma unroll
        for (int j = 0; j < 4; ++j) {
            const float* vv = &v[j].x;
            #pragma unroll
            for (int x = 0; x < 4; ++x) {
                float xv = vv[x];
                ar[0][x] = fmaf(xv, cB0, ar[0][x]);  ai[0][x] = fmaf(xv, sB0, ai[0][x]);
                ar[1][x] = fmaf(xv, cB1, ar[1][x]);  ai[1][x] = fmaf(xv, sB1, ai[1][x]);
                ar[2][x] = fmaf(xv, cB2, ar[2][x]);  ai[2][x] = fmaf(xv, sB2, ai[2][x]);
            }
            if (j < 3) {
                float t;
                t = fmaf(cB0, CF0,  sB0 * SF0);  sB0 = fmaf(sB0, CF0, -cB0 * SF0);  cB0 = t;
                t = fmaf(cB1, CF1,  sB1 * SF1);  sB1 = fmaf(sB1, CF1, -cB1 * SF1);  cB1 = t;
                t = fmaf(cB2, CF2,  sB2 * SF2);  sB2 = fmaf(sB2, CF2, -cB2 * SF2);  cB2 = t;
            }
        }

        // ---- prefetch next batch's q: in flight across the whole tail ----
        if (b + 1 < NB) {
            const float4* qn = (const float4*)q + (size_t)(b + 1) * bstr4
                               + (size_t)n * (SLAB / 4);
            #pragma unroll
            for (int j = 0; j < 4; ++j)
                v[j] = qn[(4 * p + j) * 16 + c];
        }

        // ---- warp combine + per-warp partials ----
        #pragma unroll
        for (int m = 0; m < 3; ++m)
            #pragma unroll
            for (int x = 0; x < 4; ++x) {
                ar[m][x] += __shfl_xor_sync(0xffffffffu, ar[m][x], 16);
                ai[m][x] += __shfl_xor_sync(0xffffffffu, ai[m][x], 16);
            }
        if (lane < 16) {
            #pragma unroll
            for (int m = 0; m < 3; ++m) {
                sXp4[warp][2 * m    ][lane] = make_float4(ar[m][0], ar[m][1], ar[m][2], ar[m][3]);
                sXp4[warp][2 * m + 1][lane] = make_float4(ai[m][0], ai[m][1], ai[m][2], ai[m][3]);
            }
        }
        __syncthreads();

        // ---- reduce 8 warp-partials -> X ----
        if (tid < 192) {
            const float* sf = (const float*)sXp4;
            float xr = 0.f, xi = 0.f;
            #pragma unroll
            for (int w = 0; w < 8; ++w) {
                xr += sf[w * 384 + (2 * m_    ) * 64 + ho];
                xi += sf[w * 384 + (2 * m_ + 1) * 64 + ho];
            }
            sX[2 * m_    ][ho] = xr;
            sX[2 * m_ + 1][ho] = xi;
        }
        __syncthreads();

        // ---- C: complex 16x16 channel mix, weights from smem ----
        if (tid < 192) {
            const float* wRp = sW1 + h * WPAD + o * 3 + m_;
            const float* wIp = sW2 + h * WPAD + o * 3 + m_;
            float yr = 0.f, yi = 0.f;
            #pragma unroll
            for (int i = 0; i < 16; ++i) {
                float wr = wRp[i * 48];
                float wi = wIp[i * 48];
                float xr = sX[2 * m_    ][(h << 4) + i];
                float xi = sX[2 * m_ + 1][(h << 4) + i];
                yr = fmaf(xr, wr, yr);  yr = fmaf(-xi, wi, yr);
                yi = fmaf(xr, wi, yi);  yi = fmaf( xi, wr, yi);
            }
            sY[2 * m_    ][ho] = yr;
            sY[2 * m_ + 1][ho] = yi;
        }
        __syncthreads();

        // ---- D: 3-bin synthesis, register twiddle recurrence, float4 stores ----
        float4* o4 = (float4*)out + (size_t)b * bstr4 + (size_t)n * (SLAB / 4);
        #pragma unroll
        for (int r = 0; r < 4; ++r) {
            int f4i = tid + (r << 8);
            int hd  = f4i >> 4;
            float y0  = sY[0][hd] * 0.015625f;
            float y1r = sY[2][hd] * 0.03125f, y1i = sY[3][hd] * 0.03125f;
            float y2r = sY[4][hd] * 0.03125f, y2i = sY[5][hd] * 0.03125f;
            float cc1 = c1b, ss1 = s1b, cc2 = c2b, ss2 = s2b;
            float4 vv4;  float* vp = &vv4.x;
            #pragma unroll
            for (int j = 0; j < 4; ++j) {
                float acc = y0;
                acc = fmaf(y1r, cc1, acc);  acc = fmaf(-y1i, ss1, acc);
                acc = fmaf(y2r, cc2, acc);  acc = fmaf(-y2i, ss2, acc);
                vp[j] = acc;
                if (j < 3) {
                    float t;
                    t = fmaf(cc1, R1C, -ss1 * R1S);  ss1 = fmaf(ss1, R1C, cc1 * R1S);  cc1 = t;
                    t = fmaf(cc2, R2C, -ss2 * R2S);  ss2 = fmaf(ss2, R2C, cc2 * R2S);  cc2 = t;
                }
            }
            o4[f4i] = vv4;
        }
        // Hazard check: sXp4/sX rewritten only after next iter's work preceding
        // bar1; all cross-thread reads of this iter completed before bar2/bar3.
        // sY read in D (after bar3) is rewritten only after next bar2, which
        // requires every thread to have passed next bar1, hence finished D.
    }
}

extern "C" void kernel_launch(void* const* d_in, const int* in_sizes, int n_in,
                              void* d_out, int out_size)
{
    // metadata order: q, k, v, mask, weights1, weights2 (k, v, mask unused)
    const float* q  = (const float*)d_in[0];
    const float* w1 = (const float*)d_in[4];
    const float* w2 = (const float*)d_in[5];
    float* out = (float*)d_out;

    fourier_pipe_kernel<<<NN, 256>>>(q, w1, w2, out);
}

// round 8
// speedup vs baseline: 1.3333x; 1.0533x over previous
#include <cuda_runtime.h>
#include <cstdint>

// FourierBlock: out = irfft3bins( einsum(rfft(q)[bins 1,4,5], W1+iW2) )
// q: (B=8, N=2000, L=64, H=4, E=16); weights (N,H,E,E,3). k,v,mask unused.
// One CTA per node, persistent over b. q staged via cp.async double buffer
// (no registers held across the tail), weights in smem, 3 CTAs/SM target.

#define NB 8
#define NN 2000
#define SLAB 4096          // floats per (b,n) slab
#define WNODE 3072         // floats per node per weight tensor
#define WPAD 776           // padded per-h smem stride in floats

// dynamic smem layout (floats)
#define OFF_QBUF  0                    // 2 * 4096
#define OFF_W1    8192                 // 3104
#define OFF_W2    11296                // 3104
#define OFF_XP    14400                // 3072 (8 warps * 6 * 16 float4 -> floats)
#define OFF_X     17472                // 384
#define OFF_Y     17856                // 384
#define SMEM_FLOATS 18240
#define SMEM_BYTES (SMEM_FLOATS * 4)   // 72960

// cos(2*pi*k/64); sin(2*pi*k/64) = COS64[(k+48)&63]
__device__ const float COS64[64] = {
     1.000000000f,  0.995184727f,  0.980785280f,  0.956940336f,
     0.923879533f,  0.881921264f,  0.831469612f,  0.773010453f,
     0.707106781f,  0.634393284f,  0.555570233f,  0.471396737f,
     0.382683432f,  0.290284677f,  0.195090322f,  0.098017140f,
     0.000000000f, -0.098017140f, -0.195090322f, -0.290284677f,
    -0.382683432f, -0.471396737f, -0.555570233f, -0.634393284f,
    -0.707106781f, -0.773010453f, -0.831469612f, -0.881921264f,
    -0.923879533f, -0.956940336f, -0.980785280f, -0.995184727f,
    -1.000000000f, -0.995184727f, -0.980785280f, -0.956940336f,
    -0.923879533f, -0.881921264f, -0.831469612f, -0.773010453f,
    -0.707106781f, -0.634393284f, -0.555570233f, -0.471396737f,
    -0.382683432f, -0.290284677f, -0.195090322f, -0.098017140f,
     0.000000000f,  0.098017140f,  0.195090322f,  0.290284677f,
     0.382683432f,  0.471396737f,  0.555570233f,  0.634393284f,
     0.707106781f,  0.773010453f,  0.831469612f,  0.881921264f,
     0.923879533f,  0.956940336f,  0.980785280f,  0.995184727f
};

__device__ __forceinline__ void cp_async16(uint32_t dst, const void* src) {
    asm volatile("cp.async.cg.shared.global [%0], [%1], 16;\n" :: "r"(dst), "l"(src));
}
__device__ __forceinline__ void cp_commit() {
    asm volatile("cp.async.commit_group;\n" ::: "memory");
}
__device__ __forceinline__ void cp_wait1() {
    asm volatile("cp.async.wait_group 1;\n" ::: "memory");
}

__global__ __launch_bounds__(256, 3) void fourier_cp_kernel(
    const float* __restrict__ q,
    const float* __restrict__ w1,
    const float* __restrict__ w2,
    float* __restrict__ out)
{
    extern __shared__ float smem[];
    float* sQ  = smem + OFF_QBUF;   // [2][4096]
    float* sW1 = smem + OFF_W1;     // [4][WPAD]
    float* sW2 = smem + OFF_W2;
    float* sXp = smem + OFF_XP;     // [8 warps][6][16] float4-packed
    float* sX  = smem + OFF_X;      // [6][64]
    float* sY  = smem + OFF_Y;      // [6][64]

    const int n    = blockIdx.x;
    const int tid  = threadIdx.x;
    const int lane = tid & 31;
    const int warp = tid >> 5;
    const int c    = tid & 15;      // float4 column (hi group of 4)
    const int p    = tid >> 4;      // l-row group: l = 4p..4p+3

    const size_t bstr4 = (size_t)NN * (SLAB / 4);  // float4 stride per batch
    // this thread's 4 fetch/consume slots (float4 index within slab)
    const int s0 = (4 * p) * 16 + c;

    const uint32_t qb_u32 = (uint32_t)__cvta_generic_to_shared(sQ);

    // ---- prologue: stage batch 0 ----
    {
        const float4* q0 = (const float4*)q + (size_t)n * (SLAB / 4);
        #pragma unroll
        for (int j = 0; j < 4; ++j)
            cp_async16(qb_u32 + (uint32_t)(s0 + 16 * j) * 16u, q0 + s0 + 16 * j);
        cp_commit();
    }

    // ---- cooperative weight stage: raw layout, coalesced, padded per h ----
    {
        const float4* a4 = (const float4*)(w1 + (size_t)n * WNODE);
        const float4* b4 = (const float4*)(w2 + (size_t)n * WNODE);
        #pragma unroll
        for (int r = 0; r < 3; ++r) {
            int g4  = tid + 256 * r;        // 0..767
            int h   = g4 / 192;
            int rem = g4 - h * 192;
            ((float4*)sW1)[h * (WPAD / 4) + rem] = a4[g4];
            ((float4*)sW2)[h * (WPAD / 4) + rem] = b4[g4];
        }
    }

    // ---- twiddle bases (once per CTA) ----
    const float CF0 = 0.995184727f, SF0 = 0.098017140f;   // e^{-i*2pi*1/64}
    const float CF1 = 0.923879533f, SF1 = 0.382683432f;   // f=4
    const float CF2 = 0.881921264f, SF2 = 0.471396737f;   // f=5
    float cB0b, sB0b, cB1b, sB1b, cB2b, sB2b;
    {
        int l0 = 4 * p;
        int k0 = l0 & 63, k1 = (4 * l0) & 63, k2 = (5 * l0) & 63;
        cB0b = COS64[k0];  sB0b = -COS64[(k0 + 48) & 63];
        cB1b = COS64[k1];  sB1b = -COS64[(k1 + 48) & 63];
        cB2b = COS64[k2];  sB2b = -COS64[(k2 + 48) & 63];
    }
    const float R1C = 0.995184727f, R1S = 0.098017140f;   // e^{+i*2pi/64}
    const float R2C = 0.980785280f, R2S = 0.195090322f;   // e^{+i*4pi/64}
    float c1b, s1b, c2b, s2b;
    {
        int l0 = (tid & 15) << 2;
        c1b = COS64[l0];              s1b = COS64[(l0 + 48) & 63];
        c2b = COS64[(2 * l0) & 63];   s2b = COS64[(2 * l0 + 48) & 63];
    }

    const int m_ = tid >> 6;     // 0..2 (valid for tid < 192)
    const int ho = tid & 63;
    const int h  = ho >> 4;
    const int o  = ho & 15;

    for (int b = 0; b < NB; ++b) {
        // ---- prefetch next batch into the other buffer (no regs held) ----
        if (b + 1 < NB) {
            const float4* qn = (const float4*)q + (size_t)(b + 1) * bstr4
                               + (size_t)n * (SLAB / 4);
            uint32_t dst = qb_u32 + (uint32_t)(((b + 1) & 1) * SLAB) * 4u;
            #pragma unroll
            for (int j = 0; j < 4; ++j)
                cp_async16(dst + (uint32_t)(s0 + 16 * j) * 16u, qn + s0 + 16 * j);
        }
        cp_commit();          // one group per iteration (possibly empty)
        cp_wait1();           // batch b's group complete (per-thread ordering)

        // ---- consume own staged bytes: 4 conflict-free LDS.128 ----
        float4 v[4];
        {
            const float4* qs = (const float4*)(sQ + (b & 1) * SLAB);
            #pragma unroll
            for (int j = 0; j < 4; ++j)
                v[j] = qs[s0 + 16 * j];
        }

        // ---- 3-bin DFT over this thread's 4 l-rows ----
        float cB0 = cB0b, sB0 = sB0b, cB1 = cB1b, sB1 = sB1b, cB2 = cB2b, sB2 = sB2b;
        float ar[3][4], ai[3][4];
        #pragma unroll
        for (int m = 0; m < 3; ++m)
            #pragma unroll
            for (int x = 0; x < 4; ++x) { ar[m][x] = 0.f; ai[m][x] = 0.f; }

        #pragma unroll
        for (int j = 0; j < 4; ++j) {
            const float* vv = &v[j].x;
            #pragma unroll
            for (int x = 0; x < 4; ++x) {
                float xv = vv[x];
                ar[0][x] = fmaf(xv, cB0, ar[0][x]);  ai[0][x] = fmaf(xv, sB0, ai[0][x]);
                ar[1][x] = fmaf(xv, cB1, ar[1][x]);  ai[1][x] = fmaf(xv, sB1, ai[1][x]);
                ar[2][x] = fmaf(xv, cB2, ar[2][x]);  ai[2][x] = fmaf(xv, sB2, ai[2][x]);
            }
            if (j < 3) {
                float t;
                t = fmaf(cB0, CF0,  sB0 * SF0);  sB0 = fmaf(sB0, CF0, -cB0 * SF0);  cB0 = t;
                t = fmaf(cB1, CF1,  sB1 * SF1);  sB1 = fmaf(sB1, CF1, -cB1 * SF1);  cB1 = t;
                t = fmaf(cB2, CF2,  sB2 * SF2);  sB2 = fmaf(sB2, CF2, -cB2 * SF2);  cB2 = t;
            }
        }

        // ---- warp combine + per-warp partials ----
        #pragma unroll
        for (int m = 0; m < 3; ++m)
            #pragma unroll
            for (int x = 0; x < 4; ++x) {
                ar[m][x] += __shfl_xor_sync(0xffffffffu, ar[m][x], 16);
                ai[m][x] += __shfl_xor_sync(0xffffffffu, ai[m][x], 16);
            }
        if (lane < 16) {
            float4* xp4 = (float4*)sXp + warp * 96 + lane;   // [warp][6][16]
            #pragma unroll
            for (int m = 0; m < 3; ++m) {
                xp4[(2 * m    ) * 16] = make_float4(ar[m][0], ar[m][1], ar[m][2], ar[m][3]);
                xp4[(2 * m + 1) * 16] = make_float4(ai[m][0], ai[m][1], ai[m][2], ai[m][3]);
            }
        }
        __syncthreads();

        // ---- reduce 8 warp-partials -> X ----
        if (tid < 192) {
            float xr = 0.f, xi = 0.f;
            #pragma unroll
            for (int w = 0; w < 8; ++w) {
                xr += sXp[w * 384 + (2 * m_    ) * 64 + ho];
                xi += sXp[w * 384 + (2 * m_ + 1) * 64 + ho];
            }
            sX[(2 * m_    ) * 64 + ho] = xr;
            sX[(2 * m_ + 1) * 64 + ho] = xi;
        }
        __syncthreads();

        // ---- C: complex 16x16 channel mix, weights from smem ----
        if (tid < 192) {
            const float* wRp = sW1 + h * WPAD + o * 3 + m_;
            const float* wIp = sW2 + h * WPAD + o * 3 + m_;
            float yr = 0.f, yi = 0.f;
            #pragma unroll
            for (int i = 0; i < 16; ++i) {
                float wr = wRp[i * 48];
                float wi = wIp[i * 48];
                float xr = sX[(2 * m_    ) * 64 + (h << 4) + i];
                float xi = sX[(2 * m_ + 1) * 64 + (h << 4) + i];
                yr = fmaf(xr, wr, yr);  yr = fmaf(-xi, wi, yr);
                yi = fmaf(xr, wi, yi);  yi = fmaf( xi, wr, yi);
            }
            sY[(2 * m_    ) * 64 + ho] = yr;
            sY[(2 * m_ + 1) * 64 + ho] = yi;
        }
        __syncthreads();

        // ---- D: 3-bin synthesis, register twiddle recurrence, float4 stores ----
        float4* o4 = (float4*)out + (size_t)b * bstr4 + (size_t)n * (SLAB / 4);
        #pragma unroll
        for (int r = 0; r < 4; ++r) {
            int f4i = tid + (r << 8);
            int hd  = f4i >> 4;
            float y0  = sY[0 * 64 + hd] * 0.015625f;
            float y1r = sY[2 * 64 + hd] * 0.03125f, y1i = sY[3 * 64 + hd] * 0.03125f;
            float y2r = sY[4 * 64 + hd] * 0.03125f, y2i = sY[5 * 64 + hd] * 0.03125f;
            float cc1 = c1b, ss1 = s1b, cc2 = c2b, ss2 = s2b;
            float4 vv4;  float* vp = &vv4.x;
            #pragma unroll
            for (int j = 0; j < 4; ++j) {
                float acc = y0;
                acc = fmaf(y1r, cc1, acc);  acc = fmaf(-y1i, ss1, acc);
                acc = fmaf(y2r, cc2, acc);  acc = fmaf(-y2i, ss2, acc);
                vp[j] = acc;
                if (j < 3) {
                    float t;
                    t = fmaf(cc1, R1C, -ss1 * R1S);  ss1 = fmaf(ss1, R1C, cc1 * R1S);  cc1 = t;
                    t = fmaf(cc2, R2C, -ss2 * R2S);  ss2 = fmaf(ss2, R2C, cc2 * R2S);  cc2 = t;
                }
            }
            o4[f4i] = vv4;
        }
        // Hazards: qbuf slot (b&1) rewritten only at iter b+2 by the same thread
        // that consumed it at iter b (program order). sXp/sX/sY protected by the
        // three barriers exactly as in R5.
    }
}

extern "C" void kernel_launch(void* const* d_in, const int* in_sizes, int n_in,
                              void* d_out, int out_size)
{
    // metadata order: q, k, v, mask, weights1, weights2 (k, v, mask unused)
    const float* q  = (const float*)d_in[0];
    const float* w1 = (const float*)d_in[4];
    const float* w2 = (const float*)d_in[5];
    float* out = (float*)d_out;

    static bool attr_set = false;
    if (!attr_set) {
        cudaFuncSetAttribute(fourier_cp_kernel,
                             cudaFuncAttributeMaxDynamicSharedMemorySize, SMEM_BYTES);
        attr_set = true;
    }
    fourier_cp_kernel<<<NN, 256, SMEM_BYTES>>>(q, w1, w2, out);
}

// round 9
// speedup vs baseline: 1.4302x; 1.0726x over previous
#include <cuda_runtime.h>
#include <cstdint>

// FourierBlock: out = irfft3bins( einsum(rfft(q)[bins 1,4,5], W1+iW2) )
// q: (B=8, N=2000, L=64, H=4, E=16); weights (N,H,E,E,3). k,v,mask unused.
//
// Column-DFT layout: one CTA per node, 4 independent 64-thread groups, each
// group owns one batch at a time (b = g, then g+4). Thread hi accumulates
// X[m][hi] over all 64 l (coalesced LDG.32). Stage C exchanges X via warp
// shuffles (no smem, no barrier). Only 2 named barriers (64 threads) per batch.

#define NB 8
#define NN 2000
#define SLAB 4096
#define WNODE 3072
#define WHP 784            // padded per-h stride in transposed weight smem

// cos(2*pi*k/64); sin(2*pi*k/64) = COS64[(k+48)&63]
__device__ const float COS64[64] = {
     1.000000000f,  0.995184727f,  0.980785280f,  0.956940336f,
     0.923879533f,  0.881921264f,  0.831469612f,  0.773010453f,
     0.707106781f,  0.634393284f,  0.555570233f,  0.471396737f,
     0.382683432f,  0.290284677f,  0.195090322f,  0.098017140f,
     0.000000000f, -0.098017140f, -0.195090322f, -0.290284677f,
    -0.382683432f, -0.471396737f, -0.555570233f, -0.634393284f,
    -0.707106781f, -0.773010453f, -0.831469612f, -0.881921264f,
    -0.923879533f, -0.956940336f, -0.980785280f, -0.995184727f,
    -1.000000000f, -0.995184727f, -0.980785280f, -0.956940336f,
    -0.923879533f, -0.881921264f, -0.831469612f, -0.773010453f,
    -0.707106781f, -0.634393284f, -0.555570233f, -0.471396737f,
    -0.382683432f, -0.290284677f, -0.195090322f, -0.098017140f,
     0.000000000f,  0.098017140f,  0.195090322f,  0.290284677f,
     0.382683432f,  0.471396737f,  0.555570233f,  0.634393284f,
     0.707106781f,  0.773010453f,  0.831469612f,  0.881921264f,
     0.923879533f,  0.956940336f,  0.980785280f,  0.995184727f
};

__global__ __launch_bounds__(256, 4) void fourier_col_kernel(
    const float* __restrict__ q,
    const float* __restrict__ w1,
    const float* __restrict__ w2,
    float* __restrict__ out)
{
    __shared__ float sTwB[64 * 8];        // per l: {c1,-s1, c4,-s4, c5,-s5, 0,0}
    __shared__ float sWT1[4 * WHP];       // transposed: [h][(m*16+i)*16 + o]
    __shared__ float sWT2[4 * WHP];
    __shared__ float sY[4][5 * 64];       // per group: prescaled {y0, y1r, y1i, y2r, y2i}

    const int n    = blockIdx.x;
    const int tid  = threadIdx.x;
    const int g    = tid >> 6;            // group 0..3
    const int gtid = tid & 63;            // hi / ho within group
    const int lane = tid & 31;
    const int h    = gtid >> 4;
    const int o    = gtid & 15;

    // ---- init: analysis twiddle table ----
    if (tid < 64) {
        int l  = tid;
        int k0 = l & 63, k1 = (4 * l) & 63, k2 = (5 * l) & 63;
        float* r = sTwB + l * 8;
        r[0] = COS64[k0];  r[1] = -COS64[(k0 + 48) & 63];
        r[2] = COS64[k1];  r[3] = -COS64[(k1 + 48) & 63];
        r[4] = COS64[k2];  r[5] = -COS64[(k2 + 48) & 63];
        r[6] = 0.f;        r[7] = 0.f;
    }

    // ---- init: weights, transposed for conflict-free stage-C reads ----
    {
        const float4* a4 = (const float4*)(w1 + (size_t)n * WNODE);
        const float4* b4 = (const float4*)(w2 + (size_t)n * WNODE);
        #pragma unroll
        for (int r = 0; r < 3; ++r) {
            int g4 = tid + 256 * r;               // 0..767
            float4 av = a4[g4];
            float4 bv = b4[g4];
            const float* ap = &av.x;
            const float* bp = &bv.x;
            #pragma unroll
            for (int e = 0; e < 4; ++e) {
                int rid = 4 * g4 + e;              // h*768 + i*48 + o*3 + m
                int hh  = rid >> 9;                 // /768? no: use exact divides
                // rid / 768:
                hh = rid / 768;
                int r2 = rid - hh * 768;
                int ii = r2 / 48;
                int r3 = r2 - ii * 48;
                int oo = r3 / 3;
                int mm = r3 - oo * 3;
                int dst = hh * WHP + (mm * 16 + ii) * 16 + oo;
                sWT1[dst] = ap[e];
                sWT2[dst] = bp[e];
            }
        }
    }
    __syncthreads();

    // D-stage twiddles for this thread's 4 l values (l = 4*(gtid&15)+j),
    // prescaled: freq-1/2 carry 2/64, y0 carries 1/64 (applied at sY write).
    float c1t[4], s1t[4], c2t[4], s2t[4];
    {
        int l0 = (gtid & 15) << 2;
        #pragma unroll
        for (int j = 0; j < 4; ++j) {
            int l  = l0 + j;
            int l2 = (2 * l) & 63;
            c1t[j] = COS64[l];                 s1t[j] = COS64[(l + 48) & 63];
            c2t[j] = COS64[l2];                s2t[j] = COS64[(l2 + 48) & 63];
        }
    }

    for (int ob = 0; ob < 2; ++ob) {
        const int b = ob * 4 + g;
        const size_t slab = ((size_t)b * NN + n) * SLAB;

        // ---- B: column DFT. thread hi walks 64 l values (coalesced LDG) ----
        float xr0 = 0.f, xi0 = 0.f, xr1 = 0.f, xi1 = 0.f, xr2 = 0.f, xi2 = 0.f;
        {
            const float* qp = q + slab + gtid;
            #pragma unroll 16
            for (int l = 0; l < 64; ++l) {
                float x  = __ldg(qp + l * 64);
                float4 t4 = *(const float4*)(sTwB + l * 8);
                float2 t2 = *(const float2*)(sTwB + l * 8 + 4);
                xr0 = fmaf(x, t4.x, xr0);  xi0 = fmaf(x, t4.y, xi0);
                xr1 = fmaf(x, t4.z, xr1);  xi1 = fmaf(x, t4.w, xi1);
                xr2 = fmaf(x, t2.x, xr2);  xi2 = fmaf(x, t2.y, xi2);
            }
        }

        // ---- C: complex 16x16 mix via warp shuffles + smem weights ----
        float yr0 = 0.f, yi1r = 0.f, yi1i = 0.f, yi2r = 0.f, yi2i = 0.f;
        {
            const int sb = lane & 16;
            const float* wA = sWT1 + h * WHP + o;
            const float* wB = sWT2 + h * WHP + o;
            #pragma unroll
            for (int i = 0; i < 16; ++i) {
                int src = sb | i;
                float a0 = __shfl_sync(0xffffffffu, xr0, src);
                float b0 = __shfl_sync(0xffffffffu, xi0, src);
                float a1 = __shfl_sync(0xffffffffu, xr1, src);
                float b1 = __shfl_sync(0xffffffffu, xi1, src);
                float a2 = __shfl_sync(0xffffffffu, xr2, src);
                float b2 = __shfl_sync(0xffffffffu, xi2, src);
                float w0r = wA[(0 * 16 + i) * 16], w0i = wB[(0 * 16 + i) * 16];
                float w1r = wA[(1 * 16 + i) * 16], w1i = wB[(1 * 16 + i) * 16];
                float w2r = wA[(2 * 16 + i) * 16], w2i = wB[(2 * 16 + i) * 16];
                // bin 0 output: only real part survives irfft
                yr0  = fmaf(a0, w0r, yr0);   yr0  = fmaf(-b0, w0i, yr0);
                yi1r = fmaf(a1, w1r, yi1r);  yi1r = fmaf(-b1, w1i, yi1r);
                yi1i = fmaf(a1, w1i, yi1i);  yi1i = fmaf( b1, w1r, yi1i);
                yi2r = fmaf(a2, w2r, yi2r);  yi2r = fmaf(-b2, w2i, yi2r);
                yi2i = fmaf(a2, w2i, yi2i);  yi2i = fmaf( b2, w2r, yi2i);
            }
        }

        // ---- publish Y (prescaled), group-local barrier ----
        {
            float* sy = sY[g];
            sy[0 * 64 + gtid] = yr0  * 0.015625f;
            sy[1 * 64 + gtid] = yi1r * 0.03125f;
            sy[2 * 64 + gtid] = yi1i * 0.03125f;
            sy[3 * 64 + gtid] = yi2r * 0.03125f;
            sy[4 * 64 + gtid] = yi2i * 0.03125f;
        }
        asm volatile("bar.sync %0, %1;" :: "r"(g + 1), "r"(64) : "memory");

        // ---- D: 3-bin synthesis, coalesced float4 stores ----
        {
            const float* sy = sY[g];
            float4* o4 = (float4*)(out + slab);
            #pragma unroll
            for (int r = 0; r < 16; ++r) {
                int f4i = gtid + (r << 6);
                int hd  = f4i >> 4;
                float y0  = sy[hd];
                float y1r = sy[64 + hd],  y1i = sy[128 + hd];
                float y2r = sy[192 + hd], y2i = sy[256 + hd];
                float4 vv;  float* vp = &vv.x;
                #pragma unroll
                for (int j = 0; j < 4; ++j) {
                    float acc = y0;
                    acc = fmaf(y1r, c1t[j], acc);  acc = fmaf(-y1i, s1t[j], acc);
                    acc = fmaf(y2r, c2t[j], acc);  acc = fmaf(-y2i, s2t[j], acc);
                    vp[j] = acc;
                }
                o4[f4i] = vv;
            }
        }
        // protect sY against next batch's writes
        asm volatile("bar.sync %0, %1;" :: "r"(g + 1), "r"(64) : "memory");
    }
}

extern "C" void kernel_launch(void* const* d_in, const int* in_sizes, int n_in,
                              void* d_out, int out_size)
{
    // metadata order: q, k, v, mask, weights1, weights2 (k, v, mask unused)
    const float* q  = (const float*)d_in[0];
    const float* w1 = (const float*)d_in[4];
    const float* w2 = (const float*)d_in[5];
    float* out = (float*)d_out;

    fourier_col_kernel<<<NN, 256>>>(q, w1, w2, out);
}

// round 11
// speedup vs baseline: 1.4383x; 1.0057x over previous
#include <cuda_runtime.h>
#include <cstdint>

// FourierBlock: out = irfft3bins( einsum(rfft(q)[bins 1,4,5], W1+iW2) )
// q: (B=8, N=2000, L=64, H=4, E=16); weights (N,H,E,E,3). k,v,mask unused.
//
// Column-DFT: one CTA per node, 4 independent 64-thread groups, each group
// owns one batch at a time (b = g, g+4). Thread hi accumulates X[m][hi] over
// all 64 l (coalesced LDG.32). Twiddles: one LDS.128 per l (bins 1,4), bin 5
// derived via angle addition. Stage C: warp shuffles + float2 weight LDS.64.

#define NB 8
#define NN 2000
#define SLAB 4096
#define WNODE 3072
#define WHP2 776           // per-h stride in float2 units (768 + 8 pad)

// cos(2*pi*k/64); sin(2*pi*k/64) = COS64[(k+48)&63]
__device__ const float COS64[64] = {
     1.000000000f,  0.995184727f,  0.980785280f,  0.956940336f,
     0.923879533f,  0.881921264f,  0.831469612f,  0.773010453f,
     0.707106781f,  0.634393284f,  0.555570233f,  0.471396737f,
     0.382683432f,  0.290284677f,  0.195090322f,  0.098017140f,
     0.000000000f, -0.098017140f, -0.195090322f, -0.290284677f,
    -0.382683432f, -0.471396737f, -0.555570233f, -0.634393284f,
    -0.707106781f, -0.773010453f, -0.831469612f, -0.881921264f,
    -0.923879533f, -0.956940336f, -0.980785280f, -0.995184727f,
    -1.000000000f, -0.995184727f, -0.980785280f, -0.956940336f,
    -0.923879533f, -0.881921264f, -0.831469612f, -0.773010453f,
    -0.707106781f, -0.634393284f, -0.555570233f, -0.471396737f,
    -0.382683432f, -0.290284677f, -0.195090322f, -0.098017140f,
     0.000000000f,  0.098017140f,  0.195090322f,  0.290284677f,
     0.382683432f,  0.471396737f,  0.555570233f,  0.634393284f,
     0.707106781f,  0.773010453f,  0.831469612f,  0.881921264f,
     0.923879533f,  0.956940336f,  0.980785280f,  0.995184727f
};

__global__ __launch_bounds__(256, 4) void fourier_col2_kernel(
    const float* __restrict__ q,
    const float* __restrict__ w1,
    const float* __restrict__ w2,
    float* __restrict__ out)
{
    __shared__ float4 sTw4[64];           // per l: {cos t, -sin t, cos 4t, -sin 4t}
    __shared__ float2 sWc[4 * WHP2];      // [h][(m*16+i)*16 + o] = {w1, w2}
    __shared__ float  sY[4][5 * 64];      // per group: prescaled {y0, y1r, y1i, y2r, y2i}

    const int n    = blockIdx.x;
    const int tid  = threadIdx.x;
    const int g    = tid >> 6;            // group 0..3
    const int gtid = tid & 63;            // hi / ho within group
    const int lane = tid & 31;
    const int h    = gtid >> 4;
    const int o    = gtid & 15;

    // ---- init: packed analysis twiddle table (bins 1 and 4) ----
    if (tid < 64) {
        int l  = tid;
        int k1 = l & 63, k4 = (4 * l) & 63;
        sTw4[l] = make_float4(COS64[k1], -COS64[(k1 + 48) & 63],
                              COS64[k4], -COS64[(k4 + 48) & 63]);
    }

    // ---- init: weights transposed + re/im interleaved ----
    {
        const float4* a4 = (const float4*)(w1 + (size_t)n * WNODE);
        const float4* b4 = (const float4*)(w2 + (size_t)n * WNODE);
        #pragma unroll
        for (int r = 0; r < 3; ++r) {
            int g4 = tid + 256 * r;               // 0..767
            float4 av = a4[g4];
            float4 bv = b4[g4];
            const float* ap = &av.x;
            const float* bp = &bv.x;
            #pragma unroll
            for (int e = 0; e < 4; ++e) {
                int rid = 4 * g4 + e;              // h*768 + i*48 + o*3 + m
                int hh  = rid / 768;
                int r2  = rid - hh * 768;
                int ii  = r2 / 48;
                int r3  = r2 - ii * 48;
                int oo  = r3 / 3;
                int mm  = r3 - oo * 3;
                sWc[hh * WHP2 + (mm * 16 + ii) * 16 + oo] = make_float2(ap[e], bp[e]);
            }
        }
    }
    __syncthreads();

    // D-stage twiddles for this thread's 4 l values (l = 4*(gtid&15)+j)
    float c1t[4], s1t[4], c2t[4], s2t[4];
    {
        int l0 = (gtid & 15) << 2;
        #pragma unroll
        for (int j = 0; j < 4; ++j) {
            int l  = l0 + j;
            int l2 = (2 * l) & 63;
            c1t[j] = COS64[l];   s1t[j] = COS64[(l + 48) & 63];
            c2t[j] = COS64[l2];  s2t[j] = COS64[(l2 + 48) & 63];
        }
    }

    for (int ob = 0; ob < 2; ++ob) {
        const int b = ob * 4 + g;
        const size_t slab = ((size_t)b * NN + n) * SLAB;

        // ---- B: column DFT; 1 LDG + 1 LDS.128 per l, bin5 by angle addition ----
        float xr0 = 0.f, xi0 = 0.f, xr1 = 0.f, xi1 = 0.f, xr2 = 0.f, xi2 = 0.f;
        {
            const float* qp = q + slab + gtid;
            #pragma unroll 16
            for (int l = 0; l < 64; ++l) {
                float x  = __ldg(qp + l * 64);
                float4 t = sTw4[l];
                // e^{-i5t} = (t.x + i t.y)(t.z + i t.w)
                float c5 = t.x * t.z - t.y * t.w;
                float s5 = fmaf(t.x, t.w, t.y * t.z);
                xr0 = fmaf(x, t.x, xr0);  xi0 = fmaf(x, t.y, xi0);
                xr1 = fmaf(x, t.z, xr1);  xi1 = fmaf(x, t.w, xi1);
                xr2 = fmaf(x, c5,  xr2);  xi2 = fmaf(x, s5,  xi2);
            }
        }

        // ---- C: complex 16x16 mix via warp shuffles + float2 weight loads ----
        float yr0 = 0.f, yi1r = 0.f, yi1i = 0.f, yi2r = 0.f, yi2i = 0.f;
        {
            const int sb = lane & 16;
            const float2* wP = sWc + h * WHP2 + o;
            #pragma unroll
            for (int i = 0; i < 16; ++i) {
                int src = sb | i;
                float a0 = __shfl_sync(0xffffffffu, xr0, src);
                float b0 = __shfl_sync(0xffffffffu, xi0, src);
                float a1 = __shfl_sync(0xffffffffu, xr1, src);
                float b1 = __shfl_sync(0xffffffffu, xi1, src);
                float a2 = __shfl_sync(0xffffffffu, xr2, src);
                float b2 = __shfl_sync(0xffffffffu, xi2, src);
                float2 w0 = wP[(0 * 16 + i) * 16];
                float2 w1v = wP[(1 * 16 + i) * 16];
                float2 w2v = wP[(2 * 16 + i) * 16];
                // bin 0: only the real part survives irfft
                yr0  = fmaf(a0, w0.x, yr0);    yr0  = fmaf(-b0, w0.y, yr0);
                yi1r = fmaf(a1, w1v.x, yi1r);  yi1r = fmaf(-b1, w1v.y, yi1r);
                yi1i = fmaf(a1, w1v.y, yi1i);  yi1i = fmaf( b1, w1v.x, yi1i);
                yi2r = fmaf(a2, w2v.x, yi2r);  yi2r = fmaf(-b2, w2v.y, yi2r);
                yi2i = fmaf(a2, w2v.y, yi2i);  yi2i = fmaf( b2, w2v.x, yi2i);
            }
        }

        // ---- publish Y (prescaled), group-local barrier ----
        {
            float* sy = sY[g];
            sy[0 * 64 + gtid] = yr0  * 0.015625f;
            sy[1 * 64 + gtid] = yi1r * 0.03125f;
            sy[2 * 64 + gtid] = yi1i * 0.03125f;
            sy[3 * 64 + gtid] = yi2r * 0.03125f;
            sy[4 * 64 + gtid] = yi2i * 0.03125f;
        }
        asm volatile("bar.sync %0, %1;" :: "r"(g + 1), "r"(64) : "memory");

        // ---- D: 3-bin synthesis, coalesced float4 stores ----
        {
            const float* sy = sY[g];
            float4* o4 = (float4*)(out + slab);
            #pragma unroll
            for (int r = 0; r < 16; ++r) {
                int f4i = gtid + (r << 6);
                int hd  = f4i >> 4;
                float y0  = sy[hd];
                float y1r = sy[64 + hd],  y1i = sy[128 + hd];
                float y2r = sy[192 + hd], y2i = sy[256 + hd];
                float4 vv;  float* vp = &vv.x;
                #pragma unroll
                for (int j = 0; j < 4; ++j) {
                    float acc = y0;
                    acc = fmaf(y1r, c1t[j], acc);  acc = fmaf(-y1i, s1t[j], acc);
                    acc = fmaf(y2r, c2t[j], acc);  acc = fmaf(-y2i, s2t[j], acc);
                    vp[j] = acc;
                }
                o4[f4i] = vv;
            }
        }
        // protect sY against next batch's writes
        asm volatile("bar.sync %0, %1;" :: "r"(g + 1), "r"(64) : "memory");
    }
}

extern "C" void kernel_launch(void* const* d_in, const int* in_sizes, int n_in,
                              void* d_out, int out_size)
{
    // metadata order: q, k, v, mask, weights1, weights2 (k, v, mask unused)
    const float* q  = (const float*)d_in[0];
    const float* w1 = (const float*)d_in[4];
    const float* w2 = (const float*)d_in[5];
    float* out = (float*)d_out;

    fourier_col2_kernel<<<NN, 256>>>(q, w1, w2, out);
}

// round 12
// speedup vs baseline: 1.4426x; 1.0030x over previous
#include <cuda_runtime.h>
#include <cstdint>

// FourierBlock: out = irfft3bins( einsum(rfft(q)[bins 1,4,5], W1+iW2) )
// q: (B=8, N=2000, L=64, H=4, E=16); weights (N,H,E,E,3). k,v,mask unused.
//
// Column-DFT: one CTA per node, 4 independent 64-thread groups, each group
// owns one batch (b = g, g+4). Thread hi accumulates X[m][hi] over 64 l
// (coalesced LDG.32, twiddle via one broadcast LDS.128 + angle addition).
// Stage C: warp shuffles + float2 weights. Stage D: 4-reg twiddle recurrence
// (regs <= 51 -> 5 CTAs/SM) and vectorized sY records.

#define NB 8
#define NN 2000
#define SLAB 4096
#define WNODE 3072
#define WHP2 776           // per-h stride in float2 units (768 + 8 pad)

// cos(2*pi*k/64); sin(2*pi*k/64) = COS64[(k+48)&63]
__device__ const float COS64[64] = {
     1.000000000f,  0.995184727f,  0.980785280f,  0.956940336f,
     0.923879533f,  0.881921264f,  0.831469612f,  0.773010453f,
     0.707106781f,  0.634393284f,  0.555570233f,  0.471396737f,
     0.382683432f,  0.290284677f,  0.195090322f,  0.098017140f,
     0.000000000f, -0.098017140f, -0.195090322f, -0.290284677f,
    -0.382683432f, -0.471396737f, -0.555570233f, -0.634393284f,
    -0.707106781f, -0.773010453f, -0.831469612f, -0.881921264f,
    -0.923879533f, -0.956940336f, -0.980785280f, -0.995184727f,
    -1.000000000f, -0.995184727f, -0.980785280f, -0.956940336f,
    -0.923879533f, -0.881921264f, -0.831469612f, -0.773010453f,
    -0.707106781f, -0.634393284f, -0.555570233f, -0.471396737f,
    -0.382683432f, -0.290284677f, -0.195090322f, -0.098017140f,
     0.000000000f,  0.098017140f,  0.195090322f,  0.290284677f,
     0.382683432f,  0.471396737f,  0.555570233f,  0.634393284f,
     0.707106781f,  0.773010453f,  0.831469612f,  0.881921264f,
     0.923879533f,  0.956940336f,  0.980785280f,  0.995184727f
};

__global__ __launch_bounds__(256, 5) void fourier_col3_kernel(
    const float* __restrict__ q,
    const float* __restrict__ w1,
    const float* __restrict__ w2,
    float* __restrict__ out)
{
    __shared__ float4 sTw4[64];           // per l: {cos t, -sin t, cos 4t, -sin 4t}
    __shared__ float2 sWc[4 * WHP2];      // [h][(m*16+i)*16 + o] = {w1, w2}
    __shared__ float  sY[4][64 * 8];      // per group: records of 8 floats per ho:
                                          // {y0p, y1rp, y1ip, y2rp, y2ip, pad...}

    const int n    = blockIdx.x;
    const int tid  = threadIdx.x;
    const int g    = tid >> 6;            // group 0..3
    const int gtid = tid & 63;            // hi / ho within group
    const int lane = tid & 31;
    const int h    = gtid >> 4;
    const int o    = gtid & 15;

    // ---- init: packed analysis twiddle table (bins 1 and 4) ----
    if (tid < 64) {
        int l  = tid;
        int k1 = l & 63, k4 = (4 * l) & 63;
        sTw4[l] = make_float4(COS64[k1], -COS64[(k1 + 48) & 63],
                              COS64[k4], -COS64[(k4 + 48) & 63]);
    }

    // ---- init: weights transposed + re/im interleaved ----
    {
        const float4* a4 = (const float4*)(w1 + (size_t)n * WNODE);
        const float4* b4 = (const float4*)(w2 + (size_t)n * WNODE);
        #pragma unroll
        for (int r = 0; r < 3; ++r) {
            int g4 = tid + 256 * r;               // 0..767
            float4 av = a4[g4];
            float4 bv = b4[g4];
            const float* ap = &av.x;
            const float* bp = &bv.x;
            #pragma unroll
            for (int e = 0; e < 4; ++e) {
                int rid = 4 * g4 + e;              // h*768 + i*48 + o*3 + m
                int hh  = rid / 768;
                int r2  = rid - hh * 768;
                int ii  = r2 / 48;
                int r3  = r2 - ii * 48;
                int oo  = r3 / 3;
                int mm  = r3 - oo * 3;
                sWc[hh * WHP2 + (mm * 16 + ii) * 16 + oo] = make_float2(ap[e], bp[e]);
            }
        }
    }
    __syncthreads();

    // D-stage base twiddles (4 regs) for l0 = 4*(gtid&15); rotated in-loop.
    float c1b, s1b, c2b, s2b;
    {
        int l0 = (gtid & 15) << 2;
        int l2 = (2 * l0) & 63;
        c1b = COS64[l0];  s1b = COS64[(l0 + 48) & 63];
        c2b = COS64[l2];  s2b = COS64[(l2 + 48) & 63];
    }
    const float R1C = 0.995184727f, R1S = 0.098017140f;   // e^{+i*2pi/64}
    const float R2C = 0.980785280f, R2S = 0.195090322f;   // e^{+i*4pi/64}

    for (int ob = 0; ob < 2; ++ob) {
        const int b = ob * 4 + g;
        const size_t slab = ((size_t)b * NN + n) * SLAB;

        // ---- B: column DFT; 1 LDG + 1 broadcast LDS.128 per l ----
        float xr0 = 0.f, xi0 = 0.f, xr1 = 0.f, xi1 = 0.f, xr2 = 0.f, xi2 = 0.f;
        {
            const float* qp = q + slab + gtid;
            #pragma unroll 16
            for (int l = 0; l < 64; ++l) {
                float x  = __ldg(qp + l * 64);
                float4 t = sTw4[l];
                // e^{-i5t} = (t.x + i t.y)(t.z + i t.w)
                float c5 = t.x * t.z - t.y * t.w;
                float s5 = fmaf(t.x, t.w, t.y * t.z);
                xr0 = fmaf(x, t.x, xr0);  xi0 = fmaf(x, t.y, xi0);
                xr1 = fmaf(x, t.z, xr1);  xi1 = fmaf(x, t.w, xi1);
                xr2 = fmaf(x, c5,  xr2);  xi2 = fmaf(x, s5,  xi2);
            }
        }

        // ---- C: complex 16x16 mix via warp shuffles + float2 weight loads ----
        float yr0 = 0.f, yi1r = 0.f, yi1i = 0.f, yi2r = 0.f, yi2i = 0.f;
        {
            const int sb = lane & 16;
            const float2* wP = sWc + h * WHP2 + o;
            #pragma unroll
            for (int i = 0; i < 16; ++i) {
                int src = sb | i;
                float a0 = __shfl_sync(0xffffffffu, xr0, src);
                float b0 = __shfl_sync(0xffffffffu, xi0, src);
                float a1 = __shfl_sync(0xffffffffu, xr1, src);
                float b1 = __shfl_sync(0xffffffffu, xi1, src);
                float a2 = __shfl_sync(0xffffffffu, xr2, src);
                float b2 = __shfl_sync(0xffffffffu, xi2, src);
                float2 w0  = wP[(0 * 16 + i) * 16];
                float2 w1v = wP[(1 * 16 + i) * 16];
                float2 w2v = wP[(2 * 16 + i) * 16];
                // bin 0: only the real part survives irfft
                yr0  = fmaf(a0, w0.x, yr0);    yr0  = fmaf(-b0, w0.y, yr0);
                yi1r = fmaf(a1, w1v.x, yi1r);  yi1r = fmaf(-b1, w1v.y, yi1r);
                yi1i = fmaf(a1, w1v.y, yi1i);  yi1i = fmaf( b1, w1v.x, yi1i);
                yi2r = fmaf(a2, w2v.x, yi2r);  yi2r = fmaf(-b2, w2v.y, yi2r);
                yi2i = fmaf(a2, w2v.y, yi2i);  yi2i = fmaf( b2, w2v.x, yi2i);
            }
        }

        // ---- publish Y record (prescaled), group-local barrier ----
        {
            float* rec = sY[g] + gtid * 8;
            *(float4*)rec = make_float4(yr0 * 0.015625f, yi1r * 0.03125f,
                                        yi1i * 0.03125f, yi2r * 0.03125f);
            rec[4] = yi2i * 0.03125f;
        }
        asm volatile("bar.sync %0, %1;" :: "r"(g + 1), "r"(64) : "memory");

        // ---- D: 3-bin synthesis; twiddle recurrence; vector sY reads ----
        {
            const float* sy = sY[g];
            float4* o4 = (float4*)(out + slab);
            #pragma unroll
            for (int r = 0; r < 16; ++r) {
                int f4i = gtid + (r << 6);
                int hd  = f4i >> 4;
                const float* rec = sy + hd * 8;
                float4 ya = *(const float4*)rec;   // {y0, y1r, y1i, y2r}
                float  y2i = rec[4];
                float cc1 = c1b, ss1 = s1b, cc2 = c2b, ss2 = s2b;
                float4 vv;  float* vp = &vv.x;
                #pragma unroll
                for (int j = 0; j < 4; ++j) {
                    float acc = ya.x;
                    acc = fmaf(ya.y, cc1, acc);  acc = fmaf(-ya.z, ss1, acc);
                    acc = fmaf(ya.w, cc2, acc);  acc = fmaf(-y2i, ss2, acc);
                    vp[j] = acc;
                    if (j < 3) {
                        float t;
                        t = fmaf(cc1, R1C, -ss1 * R1S);  ss1 = fmaf(ss1, R1C, cc1 * R1S);  cc1 = t;
                        t = fmaf(cc2, R2C, -ss2 * R2S);  ss2 = fmaf(ss2, R2C, cc2 * R2S);  cc2 = t;
                    }
                }
                o4[f4i] = vv;
            }
        }
        // protect sY against next batch's writes
        asm volatile("bar.sync %0, %1;" :: "r"(g + 1), "r"(64) : "memory");
    }
}

extern "C" void kernel_launch(void* const* d_in, const int* in_sizes, int n_in,
                              void* d_out, int out_size)
{
    // metadata order: q, k, v, mask, weights1, weights2 (k, v, mask unused)
    const float* q  = (const float*)d_in[0];
    const float* w1 = (const float*)d_in[4];
    const float* w2 = (const float*)d_in[5];
    float* out = (float*)d_out;

    fourier_col3_kernel<<<NN, 256>>>(q, w1, w2, out);
}

// round 13
// speedup vs baseline: 1.6235x; 1.1254x over previous
#include <cuda_runtime.h>
#include <cstdint>

// FourierBlock: out = irfft3bins( einsum(rfft(q)[bins 1,4,5], W1+iW2) )
// q: (B=8, N=2000, L=64, H=4, E=16); weights (N,H,E,E,3). k,v,mask unused.
//
// Column-DFT, one batch per 64-thread group, 8 groups per node across 2 CTAs.
// Stage B uses a 2-deep x 16-wide register load pipeline (32 LDG.32 in flight
// at burst) so DRAM latency is covered by per-warp MLP, not just warp count.

#define NB 8
#define NN 2000
#define SLAB 4096
#define WNODE 3072
#define WHP2 776           // per-h stride in float2 units (768 + 8 pad)

// cos(2*pi*k/64); sin(2*pi*k/64) = COS64[(k+48)&63]
__device__ const float COS64[64] = {
     1.000000000f,  0.995184727f,  0.980785280f,  0.956940336f,
     0.923879533f,  0.881921264f,  0.831469612f,  0.773010453f,
     0.707106781f,  0.634393284f,  0.555570233f,  0.471396737f,
     0.382683432f,  0.290284677f,  0.195090322f,  0.098017140f,
     0.000000000f, -0.098017140f, -0.195090322f, -0.290284677f,
    -0.382683432f, -0.471396737f, -0.555570233f, -0.634393284f,
    -0.707106781f, -0.773010453f, -0.831469612f, -0.881921264f,
    -0.923879533f, -0.956940336f, -0.980785280f, -0.995184727f,
    -1.000000000f, -0.995184727f, -0.980785280f, -0.956940336f,
    -0.923879533f, -0.881921264f, -0.831469612f, -0.773010453f,
    -0.707106781f, -0.634393284f, -0.555570233f, -0.471396737f,
    -0.382683432f, -0.290284677f, -0.195090322f, -0.098017140f,
     0.000000000f,  0.098017140f,  0.195090322f,  0.290284677f,
     0.382683432f,  0.471396737f,  0.555570233f,  0.634393284f,
     0.707106781f,  0.773010453f,  0.831469612f,  0.881921264f,
     0.923879533f,  0.956940336f,  0.980785280f,  0.995184727f
};

__global__ __launch_bounds__(256, 4) void fourier_col4_kernel(
    const float* __restrict__ q,
    const float* __restrict__ w1,
    const float* __restrict__ w2,
    float* __restrict__ out)
{
    __shared__ float4 sTw4[64];           // per l: {cos t, -sin t, cos 4t, -sin 4t}
    __shared__ float2 sWc[4 * WHP2];      // [h][(m*16+i)*16 + o] = {w1, w2}
    __shared__ float  sY[4][64 * 8];      // per group: 8-float records per ho

    const int half = blockIdx.x;          // 0/1 -> batches 0-3 / 4-7
    const int n    = blockIdx.y;
    const int tid  = threadIdx.x;
    const int g    = tid >> 6;            // group 0..3
    const int gtid = tid & 63;            // hi / ho within group
    const int lane = tid & 31;
    const int h    = gtid >> 4;
    const int o    = gtid & 15;

    // ---- init: packed analysis twiddle table (bins 1 and 4) ----
    if (tid < 64) {
        int l  = tid;
        int k1 = l & 63, k4 = (4 * l) & 63;
        sTw4[l] = make_float4(COS64[k1], -COS64[(k1 + 48) & 63],
                              COS64[k4], -COS64[(k4 + 48) & 63]);
    }

    // ---- init: weights transposed + re/im interleaved ----
    {
        const float4* a4 = (const float4*)(w1 + (size_t)n * WNODE);
        const float4* b4 = (const float4*)(w2 + (size_t)n * WNODE);
        #pragma unroll
        for (int r = 0; r < 3; ++r) {
            int g4 = tid + 256 * r;               // 0..767
            float4 av = a4[g4];
            float4 bv = b4[g4];
            const float* ap = &av.x;
            const float* bp = &bv.x;
            #pragma unroll
            for (int e = 0; e < 4; ++e) {
                int rid = 4 * g4 + e;              // h*768 + i*48 + o*3 + m
                int hh  = rid / 768;
                int r2  = rid - hh * 768;
                int ii  = r2 / 48;
                int r3  = r2 - ii * 48;
                int oo  = r3 / 3;
                int mm  = r3 - oo * 3;
                sWc[hh * WHP2 + (mm * 16 + ii) * 16 + oo] = make_float2(ap[e], bp[e]);
            }
        }
    }
    __syncthreads();

    const int b = half * 4 + g;
    const size_t slab = ((size_t)b * NN + n) * SLAB;
    const float* qp = q + slab + gtid;

    // ---- B: column DFT with 2-deep x 16-wide register load pipeline ----
    float xr0 = 0.f, xi0 = 0.f, xr1 = 0.f, xi1 = 0.f, xr2 = 0.f, xi2 = 0.f;
    float xa[16], xb[16];

#define LOAD16(buf, base)                                     \
    _Pragma("unroll")                                         \
    for (int j = 0; j < 16; ++j) buf[j] = __ldg(qp + ((base) + j) * 64);

#define PROC16(buf, base)                                     \
    _Pragma("unroll")                                         \
    for (int j = 0; j < 16; ++j) {                            \
        float x  = buf[j];                                    \
        float4 t = sTw4[(base) + j];                          \
        float c5 = t.x * t.z - t.y * t.w;                     \
        float s5 = fmaf(t.x, t.w, t.y * t.z);                 \
        xr0 = fmaf(x, t.x, xr0);  xi0 = fmaf(x, t.y, xi0);    \
        xr1 = fmaf(x, t.z, xr1);  xi1 = fmaf(x, t.w, xi1);    \
        xr2 = fmaf(x, c5,  xr2);  xi2 = fmaf(x, s5,  xi2);    \
    }

    LOAD16(xa, 0)
    LOAD16(xb, 16)      // 32 loads outstanding before any consume
    PROC16(xa, 0)
    LOAD16(xa, 32)
    PROC16(xb, 16)
    LOAD16(xb, 48)
    PROC16(xa, 32)
    PROC16(xb, 48)

#undef LOAD16
#undef PROC16

    // ---- C: complex 16x16 mix via warp shuffles + float2 weight loads ----
    float yr0 = 0.f, yi1r = 0.f, yi1i = 0.f, yi2r = 0.f, yi2i = 0.f;
    {
        const int sb = lane & 16;
        const float2* wP = sWc + h * WHP2 + o;
        #pragma unroll
        for (int i = 0; i < 16; ++i) {
            int src = sb | i;
            float a0 = __shfl_sync(0xffffffffu, xr0, src);
            float b0 = __shfl_sync(0xffffffffu, xi0, src);
            float a1 = __shfl_sync(0xffffffffu, xr1, src);
            float b1 = __shfl_sync(0xffffffffu, xi1, src);
            float a2 = __shfl_sync(0xffffffffu, xr2, src);
            float b2 = __shfl_sync(0xffffffffu, xi2, src);
            float2 w0  = wP[(0 * 16 + i) * 16];
            float2 w1v = wP[(1 * 16 + i) * 16];
            float2 w2v = wP[(2 * 16 + i) * 16];
            // bin 0: only the real part survives irfft
            yr0  = fmaf(a0, w0.x, yr0);    yr0  = fmaf(-b0, w0.y, yr0);
            yi1r = fmaf(a1, w1v.x, yi1r);  yi1r = fmaf(-b1, w1v.y, yi1r);
            yi1i = fmaf(a1, w1v.y, yi1i);  yi1i = fmaf( b1, w1v.x, yi1i);
            yi2r = fmaf(a2, w2v.x, yi2r);  yi2r = fmaf(-b2, w2v.y, yi2r);
            yi2i = fmaf(a2, w2v.y, yi2i);  yi2i = fmaf( b2, w2v.x, yi2i);
        }
    }

    // ---- publish Y record (prescaled), group-local barrier ----
    {
        float* rec = sY[g] + gtid * 8;
        *(float4*)rec = make_float4(yr0 * 0.015625f, yi1r * 0.03125f,
                                    yi1i * 0.03125f, yi2r * 0.03125f);
        rec[4] = yi2i * 0.03125f;
    }
    asm volatile("bar.sync %0, %1;" :: "r"(g + 1), "r"(64) : "memory");

    // ---- D: 3-bin synthesis; base twiddles + in-loop rotation; STG.128 ----
    float c1b, s1b, c2b, s2b;
    {
        int l0 = (gtid & 15) << 2;
        int l2 = (2 * l0) & 63;
        c1b = COS64[l0];  s1b = COS64[(l0 + 48) & 63];
        c2b = COS64[l2];  s2b = COS64[(l2 + 48) & 63];
    }
    const float R1C = 0.995184727f, R1S = 0.098017140f;   // e^{+i*2pi/64}
    const float R2C = 0.980785280f, R2S = 0.195090322f;   // e^{+i*4pi/64}
    {
        const float* sy = sY[g];
        float4* o4 = (float4*)(out + slab);
        #pragma unroll
        for (int r = 0; r < 16; ++r) {
            int f4i = gtid + (r << 6);
            int hd  = f4i >> 4;
            const float* rec = sy + hd * 8;
            float4 ya  = *(const float4*)rec;   // {y0, y1r, y1i, y2r}
            float  y2i = rec[4];
            float cc1 = c1b, ss1 = s1b, cc2 = c2b, ss2 = s2b;
            float4 vv;  float* vp = &vv.x;
            #pragma unroll
            for (int j = 0; j < 4; ++j) {
                float acc = ya.x;
                acc = fmaf(ya.y, cc1, acc);  acc = fmaf(-ya.z, ss1, acc);
                acc = fmaf(ya.w, cc2, acc);  acc = fmaf(-y2i, ss2, acc);
                vp[j] = acc;
                if (j < 3) {
                    float t;
                    t = fmaf(cc1, R1C, -ss1 * R1S);  ss1 = fmaf(ss1, R1C, cc1 * R1S);  cc1 = t;
                    t = fmaf(cc2, R2C, -ss2 * R2S);  ss2 = fmaf(ss2, R2C, cc2 * R2S);  cc2 = t;
                }
            }
            o4[f4i] = vv;
        }
    }
}

extern "C" void kernel_launch(void* const* d_in, const int* in_sizes, int n_in,
                              void* d_out, int out_size)
{
    // metadata order: q, k, v, mask, weights1, weights2 (k, v, mask unused)
    const float* q  = (const float*)d_in[0];
    const float* w1 = (const float*)d_in[4];
    const float* w2 = (const float*)d_in[5];
    float* out = (float*)d_out;

    dim3 grid(2, NN);   // bid = half + 2n: the two half-CTAs of a node adjacent
    fourier_col4_kernel<<<grid, 256>>>(q, w1, w2, out);
}

// round 14
// speedup vs baseline: 1.6252x; 1.0010x over previous
#include <cuda_runtime.h>
#include <cstdint>

// FourierBlock: out = irfft3bins( einsum(rfft(q)[bins 1,4,5], W1+iW2) )
// q: (B=8, N=2000, L=64, H=4, E=16); weights (N,H,E,E,3). k,v,mask unused.
//
// Column-pair DFT: one batch per 64-thread group, 8 groups/node over 2 CTAs.
// Thread owns a float2 column (c2) over its warp's 32 rows: 32 LDG.64 with a
// 2x8 double-buffered burst (16 loads in flight), warp-uniform twiddles, one
// cross-warp smem reduce. Stage C: warp shuffles + float2 weights. Stage D:
// register twiddle recurrence + STG.128.

#define NB 8
#define NN 2000
#define SLAB 4096
#define WNODE 3072
#define WHP2 776           // per-h stride in float2 units (768 + 8 pad)

// cos(2*pi*k/64); sin(2*pi*k/64) = COS64[(k+48)&63]
__device__ const float COS64[64] = {
     1.000000000f,  0.995184727f,  0.980785280f,  0.956940336f,
     0.923879533f,  0.881921264f,  0.831469612f,  0.773010453f,
     0.707106781f,  0.634393284f,  0.555570233f,  0.471396737f,
     0.382683432f,  0.290284677f,  0.195090322f,  0.098017140f,
     0.000000000f, -0.098017140f, -0.195090322f, -0.290284677f,
    -0.382683432f, -0.471396737f, -0.555570233f, -0.634393284f,
    -0.707106781f, -0.773010453f, -0.831469612f, -0.881921264f,
    -0.923879533f, -0.956940336f, -0.980785280f, -0.995184727f,
    -1.000000000f, -0.995184727f, -0.980785280f, -0.956940336f,
    -0.923879533f, -0.881921264f, -0.831469612f, -0.773010453f,
    -0.707106781f, -0.634393284f, -0.555570233f, -0.471396737f,
    -0.382683432f, -0.290284677f, -0.195090322f, -0.098017140f,
     0.000000000f,  0.098017140f,  0.195090322f,  0.290284677f,
     0.382683432f,  0.471396737f,  0.555570233f,  0.634393284f,
     0.707106781f,  0.773010453f,  0.831469612f,  0.881921264f,
     0.923879533f,  0.956940336f,  0.980785280f,  0.995184727f
};

__global__ __launch_bounds__(256, 4) void fourier_col5_kernel(
    const float* __restrict__ q,
    const float* __restrict__ w1,
    const float* __restrict__ w2,
    float* __restrict__ out)
{
    __shared__ float4 sTw4[64];           // per l: {cos t, -sin t, cos 4t, -sin 4t}
    __shared__ float2 sWc[4 * WHP2];      // [h][(m*16+i)*16 + o] = {w1, w2}
    __shared__ float2 sP[4 * 2 * 6 * 32]; // per group/warp partials: [g][w][k][c2]
    __shared__ float  sY[4][64 * 8];      // per group: 8-float records per ho

    const int half = blockIdx.x;          // 0/1 -> batches 0-3 / 4-7
    const int n    = blockIdx.y;
    const int tid  = threadIdx.x;
    const int g    = tid >> 6;            // group 0..3
    const int gtid = tid & 63;            // within group
    const int lane = tid & 31;
    const int h    = gtid >> 4;
    const int o    = gtid & 15;

    // ---- init: packed analysis twiddle table (bins 1 and 4) ----
    if (tid < 64) {
        int l  = tid;
        int k1 = l & 63, k4 = (4 * l) & 63;
        sTw4[l] = make_float4(COS64[k1], -COS64[(k1 + 48) & 63],
                              COS64[k4], -COS64[(k4 + 48) & 63]);
    }

    // ---- init: weights transposed + re/im interleaved ----
    {
        const float4* a4 = (const float4*)(w1 + (size_t)n * WNODE);
        const float4* b4 = (const float4*)(w2 + (size_t)n * WNODE);
        #pragma unroll
        for (int r = 0; r < 3; ++r) {
            int g4 = tid + 256 * r;               // 0..767
            float4 av = a4[g4];
            float4 bv = b4[g4];
            const float* ap = &av.x;
            const float* bp = &bv.x;
            #pragma unroll
            for (int e = 0; e < 4; ++e) {
                int rid = 4 * g4 + e;              // h*768 + i*48 + o*3 + m
                int hh  = rid / 768;
                int r2  = rid - hh * 768;
                int ii  = r2 / 48;
                int r3  = r2 - ii * 48;
                int oo  = r3 / 3;
                int mm  = r3 - oo * 3;
                sWc[hh * WHP2 + (mm * 16 + ii) * 16 + oo] = make_float2(ap[e], bp[e]);
            }
        }
    }
    __syncthreads();

    const int b = half * 4 + g;
    const size_t slab = ((size_t)b * NN + n) * SLAB;

    // ---- B: column-pair DFT over this warp's 32 rows ----
    const int rh = gtid >> 5;             // warp-in-group: rows rh*32 .. rh*32+31
    const int c2 = gtid & 31;             // float2 column (cols 2*c2, 2*c2+1)
    {
        const float2* qp2 = (const float2*)(q + slab) + c2;
        const int rbase = rh * 32;

        float2 a0r = {0.f,0.f}, a0i = {0.f,0.f};
        float2 a1r = {0.f,0.f}, a1i = {0.f,0.f};
        float2 a2r = {0.f,0.f}, a2i = {0.f,0.f};
        float2 xa[8], xb[8];

#define LOAD8(buf, base)                                                  \
        _Pragma("unroll")                                                 \
        for (int j = 0; j < 8; ++j)                                       \
            buf[j] = __ldg(qp2 + (size_t)(rbase + (base) + j) * 32);

#define PROC8(buf, base)                                                  \
        _Pragma("unroll")                                                 \
        for (int j = 0; j < 8; ++j) {                                     \
            float2 x = buf[j];                                            \
            float4 t = sTw4[rbase + (base) + j];                          \
            float c5 = t.x * t.z - t.y * t.w;                             \
            float s5 = fmaf(t.x, t.w, t.y * t.z);                         \
            a0r.x = fmaf(x.x, t.x, a0r.x);  a0r.y = fmaf(x.y, t.x, a0r.y);\
            a0i.x = fmaf(x.x, t.y, a0i.x);  a0i.y = fmaf(x.y, t.y, a0i.y);\
            a1r.x = fmaf(x.x, t.z, a1r.x);  a1r.y = fmaf(x.y, t.z, a1r.y);\
            a1i.x = fmaf(x.x, t.w, a1i.x);  a1i.y = fmaf(x.y, t.w, a1i.y);\
            a2r.x = fmaf(x.x, c5,  a2r.x);  a2r.y = fmaf(x.y, c5,  a2r.y);\
            a2i.x = fmaf(x.x, s5,  a2i.x);  a2i.y = fmaf(x.y, s5,  a2i.y);\
        }

        LOAD8(xa, 0)
        LOAD8(xb, 8)        // 16 LDG.64 outstanding before any consume
        PROC8(xa, 0)
        LOAD8(xa, 16)
        PROC8(xb, 8)
        LOAD8(xb, 24)
        PROC8(xa, 16)
        PROC8(xb, 24)

#undef LOAD8
#undef PROC8

        // publish per-warp partials: [g][rh][k][c2]
        float2* sPp = sP + ((g * 2 + rh) * 6) * 32 + c2;
        sPp[0 * 32] = a0r;  sPp[1 * 32] = a0i;
        sPp[2 * 32] = a1r;  sPp[3 * 32] = a1i;
        sPp[4 * 32] = a2r;  sPp[5 * 32] = a2i;
    }
    asm volatile("bar.sync %0, %1;" :: "r"(g + 1), "r"(64) : "memory");

    // ---- combine the two warps' partials: thread gtid owns X[*][gtid] ----
    float xr0, xi0, xr1, xi1, xr2, xi2;
    {
        const int e  = gtid & 1;
        const int cc = gtid >> 1;
        const float* sp0 = (const float*)(sP + (g * 2 + 0) * 6 * 32);
        const float* sp1 = (const float*)(sP + (g * 2 + 1) * 6 * 32);
        xr0 = sp0[(0 * 32 + cc) * 2 + e] + sp1[(0 * 32 + cc) * 2 + e];
        xi0 = sp0[(1 * 32 + cc) * 2 + e] + sp1[(1 * 32 + cc) * 2 + e];
        xr1 = sp0[(2 * 32 + cc) * 2 + e] + sp1[(2 * 32 + cc) * 2 + e];
        xi1 = sp0[(3 * 32 + cc) * 2 + e] + sp1[(3 * 32 + cc) * 2 + e];
        xr2 = sp0[(4 * 32 + cc) * 2 + e] + sp1[(4 * 32 + cc) * 2 + e];
        xi2 = sp0[(5 * 32 + cc) * 2 + e] + sp1[(5 * 32 + cc) * 2 + e];
    }

    // ---- C: complex 16x16 mix via warp shuffles + float2 weight loads ----
    float yr0 = 0.f, yi1r = 0.f, yi1i = 0.f, yi2r = 0.f, yi2i = 0.f;
    {
        const int sb = lane & 16;
        const float2* wP = sWc + h * WHP2 + o;
        #pragma unroll
        for (int i = 0; i < 16; ++i) {
            int src = sb | i;
            float a0 = __shfl_sync(0xffffffffu, xr0, src);
            float b0 = __shfl_sync(0xffffffffu, xi0, src);
            float a1 = __shfl_sync(0xffffffffu, xr1, src);
            float b1 = __shfl_sync(0xffffffffu, xi1, src);
            float a2 = __shfl_sync(0xffffffffu, xr2, src);
            float b2 = __shfl_sync(0xffffffffu, xi2, src);
            float2 w0  = wP[(0 * 16 + i) * 16];
            float2 w1v = wP[(1 * 16 + i) * 16];
            float2 w2v = wP[(2 * 16 + i) * 16];
            // bin 0: only the real part survives irfft
            yr0  = fmaf(a0, w0.x, yr0);    yr0  = fmaf(-b0, w0.y, yr0);
            yi1r = fmaf(a1, w1v.x, yi1r);  yi1r = fmaf(-b1, w1v.y, yi1r);
            yi1i = fmaf(a1, w1v.y, yi1i);  yi1i = fmaf( b1, w1v.x, yi1i);
            yi2r = fmaf(a2, w2v.x, yi2r);  yi2r = fmaf(-b2, w2v.y, yi2r);
            yi2i = fmaf(a2, w2v.y, yi2i);  yi2i = fmaf( b2, w2v.x, yi2i);
        }
    }

    // ---- publish Y record (prescaled), group-local barrier ----
    {
        float* rec = sY[g] + gtid * 8;
        *(float4*)rec = make_float4(yr0 * 0.015625f, yi1r * 0.03125f,
                                    yi1i * 0.03125f, yi2r * 0.03125f);
        rec[4] = yi2i * 0.03125f;
    }
    asm volatile("bar.sync %0, %1;" :: "r"(g + 1), "r"(64) : "memory");

    // ---- D: 3-bin synthesis; base twiddles + in-loop rotation; STG.128 ----
    float c1b, s1b, c2b, s2b;
    {
        int l0 = (gtid & 15) << 2;
        int l2 = (2 * l0) & 63;
        c1b = COS64[l0];  s1b = COS64[(l0 + 48) & 63];
        c2b = COS64[l2];  s2b = COS64[(l2 + 48) & 63];
    }
    const float R1C = 0.995184727f, R1S = 0.098017140f;   // e^{+i*2pi/64}
    const float R2C = 0.980785280f, R2S = 0.195090322f;   // e^{+i*4pi/64}
    {
        const float* sy = sY[g];
        float4* o4 = (float4*)(out + slab);
        #pragma unroll
        for (int r = 0; r < 16; ++r) {
            int f4i = gtid + (r << 6);
            int hd  = f4i >> 4;
            const float* rec = sy + hd * 8;
            float4 ya  = *(const float4*)rec;   // {y0, y1r, y1i, y2r}
            float  y2i = rec[4];
            float cc1 = c1b, ss1 = s1b, cc2 = c2b, ss2 = s2b;
            float4 vv;  float* vp = &vv.x;
            #pragma unroll
            for (int j = 0; j < 4; ++j) {
                float acc = ya.x;
                acc = fmaf(ya.y, cc1, acc);  acc = fmaf(-ya.z, ss1, acc);
                acc = fmaf(ya.w, cc2, acc);  acc = fmaf(-y2i, ss2, acc);
                vp[j] = acc;
                if (j < 3) {
                    float t;
                    t = fmaf(cc1, R1C, -ss1 * R1S);  ss1 = fmaf(ss1, R1C, cc1 * R1S);  cc1 = t;
                    t = fmaf(cc2, R2C, -ss2 * R2S);  ss2 = fmaf(ss2, R2C, cc2 * R2S);  cc2 = t;
                }
            }
            o4[f4i] = vv;
        }
    }
}

extern "C" void kernel_launch(void* const* d_in, const int* in_sizes, int n_in,
                              void* d_out, int out_size)
{
    // metadata order: q, k, v, mask, weights1, weights2 (k, v, mask unused)
    const float* q  = (const float*)d_in[0];
    const float* w1 = (const float*)d_in[4];
    const float* w2 = (const float*)d_in[5];
    float* out = (float*)d_out;

    dim3 grid(2, NN);   // the two half-CTAs of a node adjacent for L2 reuse
    fourier_col5_kernel<<<grid, 256>>>(q, w1, w2, out);
}